// round 12
// baseline (speedup 1.0000x reference)
#include <cuda_runtime.h>
#include <cuda_bf16.h>
#include <stdint.h>

#define D_MODEL 4096
#define RANK    32
#define TOKT    128
#define COLT    128
#define THREADS 256
#define SA      80           // bytes per sA row: 32 bf16 + 8 pad
#define SB      80           // bytes per sB row: 32 bf16 + 8 pad
#define SL      272          // bytes per sLora row: 128 bf16 + 16 pad

#define OFF_IDS  16
#define OFF_B    1024
#define OFF_A    11264
#define OFF_LORA 11264       // overlays A-tile (dead after frag hoist)
#define SM_TOTAL 28672

__device__ __forceinline__ unsigned h2u(__nv_bfloat162 h) {
    return *reinterpret_cast<unsigned*>(&h);
}
__device__ __forceinline__ __nv_bfloat162 u2h(unsigned u) {
    return *reinterpret_cast<__nv_bfloat162*>(&u);
}

__device__ __forceinline__ void mma16816(float& d0, float& d1, float& d2, float& d3,
                                         unsigned a0, unsigned a1, unsigned a2, unsigned a3,
                                         unsigned b0, unsigned b1) {
    asm volatile("mma.sync.aligned.m16n8k16.row.col.f32.bf16.bf16.f32 "
                 "{%0,%1,%2,%3}, {%4,%5,%6,%7}, {%8,%9}, {%0,%1,%2,%3};"
                 : "+f"(d0), "+f"(d1), "+f"(d2), "+f"(d3)
                 : "r"(a0), "r"(a1), "r"(a2), "r"(a3), "r"(b0), "r"(b1));
}

__global__ void __launch_bounds__(THREADS)
emb_lora_mma(const int* __restrict__ ids, const int* __restrict__ wq,
             const float* __restrict__ wscale, const float* __restrict__ A,
             const float* __restrict__ Bm, float* __restrict__ out, int ntok)
{
    __shared__ __align__(16) unsigned char sm[SM_TOTAL];

    const int tid  = threadIdx.x;
    const int wid  = tid >> 5;
    const int lane = tid & 31;
    const int g    = lane >> 2;
    const int tig  = lane & 3;
    const int gt   = wid & 3;         // warp's 16-token sub-block
    const int cw   = wid >> 2;        // warp's column half
    const int t0   = blockIdx.y * TOKT;
    const int col0 = blockIdx.x * COLT;
    int* sIds = (int*)(sm + OFF_IDS);

    if (tid < TOKT) {
        int t = t0 + tid;
        sIds[tid] = (t < ntok) ? __ldg(ids + t) : 0;
    }

    int isf = 0;
    #pragma unroll
    for (int i = 0; i < 16; ++i) {
        unsigned u = __ldg((const unsigned*)wq + i);
        if (u == 0u) continue;
        unsigned e = (u >> 23) & 0xFFu;
        isf = (e != 0u && e != 0xFFu);
        break;
    }
    __syncthreads();

    // ---- pass-0 gathers issue IMMEDIATELY (overlap tile builds + hoist) ----
    int4 q0[8];
    #pragma unroll
    for (int j = 0; j < 8; ++j) {
        int id = sIds[wid * 8 + j];
        q0[j] = __ldcs(reinterpret_cast<const int4*>(
                    wq + (size_t)id * D_MODEL + col0) + lane);
    }

    // A-tile [tok][k], SCALING=0.5 folded (exact pow2)
    #pragma unroll
    for (int i = 0; i < 8; ++i) {
        int p  = tid + i * THREADS;
        int tl = p >> 4, kp = p & 15;
        int id = sIds[tl];
        float2 v = *reinterpret_cast<const float2*>(A + (size_t)id * RANK + 2 * kp);
        *reinterpret_cast<unsigned*>(sm + OFF_A + tl * SA + kp * 4) =
            h2u(__floats2bfloat162_rn(v.x * 0.5f, v.y * 0.5f));
    }
    // B-tile [n][k] (transpose of Bm[k][n]; shared across grid.y -> L2-resident)
    #pragma unroll
    for (int i = 0; i < 8; ++i) {
        int p  = tid + i * THREADS;
        int n  = p & 127, kp = p >> 7;
        const float* bp = Bm + (size_t)(2 * kp) * D_MODEL + col0 + n;
        *reinterpret_cast<unsigned*>(sm + OFF_B + n * SB + kp * 4) =
            h2u(__floats2bfloat162_rn(__ldg(bp), __ldg(bp + D_MODEL)));
    }
    __syncthreads();

    // A fragments for BOTH token windows -> registers (16 regs)
    unsigned af[2][8];
    #pragma unroll
    for (int w = 0; w < 2; ++w) {
        const unsigned char* ar = sm + OFF_A + (w * 64 + gt * 16 + g) * SA + tig * 4;
        af[w][0] = *(const unsigned*)(ar);
        af[w][1] = *(const unsigned*)(ar + 8 * SA);
        af[w][2] = *(const unsigned*)(ar + 16);
        af[w][3] = *(const unsigned*)(ar + 8 * SA + 16);
        af[w][4] = *(const unsigned*)(ar + 32);
        af[w][5] = *(const unsigned*)(ar + 8 * SA + 32);
        af[w][6] = *(const unsigned*)(ar + 48);
        af[w][7] = *(const unsigned*)(ar + 8 * SA + 48);
    }
    __syncthreads();

    const float scale = __ldg(wscale);

    // ---- MMA pass 0: 16 tokens x 64 cols per warp -> sLora ----
    #pragma unroll
    for (int nb = 0; nb < 8; ++nb) {
        const unsigned char* bb = sm + OFF_B + (cw * 64 + nb * 8 + g) * SB + tig * 4;
        unsigned b0l = *(const unsigned*)(bb);
        unsigned b1l = *(const unsigned*)(bb + 16);
        unsigned b0h = *(const unsigned*)(bb + 32);
        unsigned b1h = *(const unsigned*)(bb + 48);
        float d0 = 0.f, d1 = 0.f, d2 = 0.f, d3 = 0.f;
        mma16816(d0, d1, d2, d3, af[0][0], af[0][1], af[0][2], af[0][3], b0l, b1l);
        mma16816(d0, d1, d2, d3, af[0][4], af[0][5], af[0][6], af[0][7], b0h, b1h);
        int colp = cw * 64 + nb * 8 + 2 * tig;
        int rt   = gt * 16 + g;
        *reinterpret_cast<unsigned*>(sm + OFF_LORA + rt * SL + colp * 2) =
            h2u(__floats2bfloat162_rn(d0, d1));
        *reinterpret_cast<unsigned*>(sm + OFF_LORA + (rt + 8) * SL + colp * 2) =
            h2u(__floats2bfloat162_rn(d2, d3));
    }

    // ---- pass-1 gathers issue NOW (overlap epilogue-0 + MMA pass 1) ----
    int4 q1[8];
    #pragma unroll
    for (int j = 0; j < 8; ++j) {
        int id = sIds[64 + wid * 8 + j];
        q1[j] = __ldcs(reinterpret_cast<const int4*>(
                    wq + (size_t)id * D_MODEL + col0) + lane);
    }
    __syncthreads();

    // ---- epilogue 0: combine + streaming store ----
    #pragma unroll
    for (int j = 0; j < 8; ++j) {
        int tl_loc = wid * 8 + j;                   // 0..63
        int t = t0 + tl_loc;
        uint2 lv = *reinterpret_cast<const uint2*>(
            sm + OFF_LORA + tl_loc * SL + lane * 8);   // cols lane*4..+3
        if (t < ntok) {
            __nv_bfloat162 l0 = u2h(lv.x), l1 = u2h(lv.y);
            float bx = isf ? __int_as_float(q0[j].x) : (float)q0[j].x;
            float by = isf ? __int_as_float(q0[j].y) : (float)q0[j].y;
            float bz = isf ? __int_as_float(q0[j].z) : (float)q0[j].z;
            float bw = isf ? __int_as_float(q0[j].w) : (float)q0[j].w;
            float4 o;
            o.x = fmaf(bx, scale, __bfloat162float(l0.x));
            o.y = fmaf(by, scale, __bfloat162float(l0.y));
            o.z = fmaf(bz, scale, __bfloat162float(l1.x));
            o.w = fmaf(bw, scale, __bfloat162float(l1.y));
            __stcs(reinterpret_cast<float4*>(
                out + (size_t)t * D_MODEL + col0 + lane * 4), o);
        }
    }
    __syncthreads();   // sLora readers done before pass-1 overwrite

    // ---- MMA pass 1 ----
    #pragma unroll
    for (int nb = 0; nb < 8; ++nb) {
        const unsigned char* bb = sm + OFF_B + (cw * 64 + nb * 8 + g) * SB + tig * 4;
        unsigned b0l = *(const unsigned*)(bb);
        unsigned b1l = *(const unsigned*)(bb + 16);
        unsigned b0h = *(const unsigned*)(bb + 32);
        unsigned b1h = *(const unsigned*)(bb + 48);
        float d0 = 0.f, d1 = 0.f, d2 = 0.f, d3 = 0.f;
        mma16816(d0, d1, d2, d3, af[1][0], af[1][1], af[1][2], af[1][3], b0l, b1l);
        mma16816(d0, d1, d2, d3, af[1][4], af[1][5], af[1][6], af[1][7], b0h, b1h);
        int colp = cw * 64 + nb * 8 + 2 * tig;
        int rt   = gt * 16 + g;
        *reinterpret_cast<unsigned*>(sm + OFF_LORA + rt * SL + colp * 2) =
            h2u(__floats2bfloat162_rn(d0, d1));
        *reinterpret_cast<unsigned*>(sm + OFF_LORA + (rt + 8) * SL + colp * 2) =
            h2u(__floats2bfloat162_rn(d2, d3));
    }
    __syncthreads();

    // ---- epilogue 1 ----
    #pragma unroll
    for (int j = 0; j < 8; ++j) {
        int tl_loc = wid * 8 + j;
        int t = t0 + 64 + tl_loc;
        uint2 lv = *reinterpret_cast<const uint2*>(
            sm + OFF_LORA + tl_loc * SL + lane * 8);
        if (t < ntok) {
            __nv_bfloat162 l0 = u2h(lv.x), l1 = u2h(lv.y);
            float bx = isf ? __int_as_float(q1[j].x) : (float)q1[j].x;
            float by = isf ? __int_as_float(q1[j].y) : (float)q1[j].y;
            float bz = isf ? __int_as_float(q1[j].z) : (float)q1[j].z;
            float bw = isf ? __int_as_float(q1[j].w) : (float)q1[j].w;
            float4 o;
            o.x = fmaf(bx, scale, __bfloat162float(l0.x));
            o.y = fmaf(by, scale, __bfloat162float(l0.y));
            o.z = fmaf(bz, scale, __bfloat162float(l1.x));
            o.w = fmaf(bw, scale, __bfloat162float(l1.y));
            __stcs(reinterpret_cast<float4*>(
                out + (size_t)t * D_MODEL + col0 + lane * 4), o);
        }
    }
}

extern "C" void kernel_launch(void* const* d_in, const int* in_sizes, int n_in,
                              void* d_out, int out_size) {
    const int*   ids    = nullptr;
    const int*   wq     = nullptr;
    const float* wscale = nullptr;
    const float* A      = nullptr;
    const float* Bm     = nullptr;

    long long ntok_ll = (long long)out_size / D_MODEL;
    long long wq_sz = 0;
    int wq_idx = -1;
    for (int i = 0; i < n_in; ++i)
        if ((long long)in_sizes[i] > wq_sz) { wq_sz = in_sizes[i]; wq_idx = i; }
    wq = (const int*)d_in[wq_idx];

    for (int i = 0; i < n_in; ++i) {
        if (i == wq_idx) continue;
        long long s = in_sizes[i];
        if (s == 1)                              wscale = (const float*)d_in[i];
        else if (s == ntok_ll)                   ids    = (const int*)d_in[i];
        else if (s == (long long)RANK * D_MODEL) Bm     = (const float*)d_in[i];
        else                                     A      = (const float*)d_in[i];
    }

    const int ntok = (int)ntok_ll;                        // 16384
    dim3 grid(D_MODEL / COLT, (ntok + TOKT - 1) / TOKT);  // (32, 128)
    emb_lora_mma<<<grid, THREADS>>>(ids, wq, wscale, A, Bm, (float*)d_out, ntok);
}

// round 13
// speedup vs baseline: 1.1557x; 1.1557x over previous
#include <cuda_runtime.h>
#include <cuda_bf16.h>
#include <stdint.h>

#define D_MODEL 4096
#define RANK    32
#define TOKT    128
#define COLT    128
#define THREADS 256
#define SA      80           // bytes per sA row: 32 bf16 + 8 pad
#define SB      80           // bytes per sB row: 32 bf16 + 8 pad
#define SL      272          // bytes per sLora row: 128 bf16 + 16 pad

#define OFF_IDS  16
#define OFF_B    1024
#define OFF_A    11264
#define OFF_LORA 11264       // overlays A-tile (dead after frag hoist)
#define SM_TOTAL 28672

__device__ __forceinline__ unsigned h2u(__nv_bfloat162 h) {
    return *reinterpret_cast<unsigned*>(&h);
}
__device__ __forceinline__ __nv_bfloat162 u2h(unsigned u) {
    return *reinterpret_cast<__nv_bfloat162*>(&u);
}

__device__ __forceinline__ void mma16816(float& d0, float& d1, float& d2, float& d3,
                                         unsigned a0, unsigned a1, unsigned a2, unsigned a3,
                                         unsigned b0, unsigned b1) {
    asm volatile("mma.sync.aligned.m16n8k16.row.col.f32.bf16.bf16.f32 "
                 "{%0,%1,%2,%3}, {%4,%5,%6,%7}, {%8,%9}, {%0,%1,%2,%3};"
                 : "+f"(d0), "+f"(d1), "+f"(d2), "+f"(d3)
                 : "r"(a0), "r"(a1), "r"(a2), "r"(a3), "r"(b0), "r"(b1));
}

__global__ void __launch_bounds__(THREADS, 3)
emb_lora_mma(const int* __restrict__ ids, const int* __restrict__ wq,
             const float* __restrict__ wscale, const float* __restrict__ A,
             const float* __restrict__ Bm, float* __restrict__ out, int ntok)
{
    __shared__ __align__(16) unsigned char sm[SM_TOTAL];

    const int tid  = threadIdx.x;
    const int wid  = tid >> 5;
    const int lane = tid & 31;
    const int g    = lane >> 2;
    const int tig  = lane & 3;
    const int gt   = wid & 3;         // warp's 16-token sub-block
    const int cw   = wid >> 2;        // warp's column half
    const int t0   = blockIdx.y * TOKT;
    const int col0 = blockIdx.x * COLT;
    int* sIds = (int*)(sm + OFF_IDS);

    if (tid < TOKT) {
        int t = t0 + tid;
        sIds[tid] = (t < ntok) ? __ldg(ids + t) : 0;
    }

    int isf = 0;
    #pragma unroll
    for (int i = 0; i < 16; ++i) {
        unsigned u = __ldg((const unsigned*)wq + i);
        if (u == 0u) continue;
        unsigned e = (u >> 23) & 0xFFu;
        isf = (e != 0u && e != 0xFFu);
        break;
    }
    __syncthreads();

    // ---- pass-0 gathers issue FIRST: drain during the whole prologue ----
    int4 q[8];
    #pragma unroll
    for (int j = 0; j < 8; ++j) {
        int id = sIds[wid * 8 + j];
        q[j] = __ldcs(reinterpret_cast<const int4*>(
                   wq + (size_t)id * D_MODEL + col0) + lane);
    }

    // A-tile [tok][k], SCALING=0.5 folded (exact pow2)
    #pragma unroll
    for (int i = 0; i < 8; ++i) {
        int p  = tid + i * THREADS;
        int tl = p >> 4, kp = p & 15;
        int id = sIds[tl];
        float2 v = *reinterpret_cast<const float2*>(A + (size_t)id * RANK + 2 * kp);
        *reinterpret_cast<unsigned*>(sm + OFF_A + tl * SA + kp * 4) =
            h2u(__floats2bfloat162_rn(v.x * 0.5f, v.y * 0.5f));
    }
    // B-tile [n][k] (transpose of Bm[k][n]; shared across grid.y -> L2-resident)
    #pragma unroll
    for (int i = 0; i < 8; ++i) {
        int p  = tid + i * THREADS;
        int n  = p & 127, kp = p >> 7;
        const float* bp = Bm + (size_t)(2 * kp) * D_MODEL + col0 + n;
        *reinterpret_cast<unsigned*>(sm + OFF_B + n * SB + kp * 4) =
            h2u(__floats2bfloat162_rn(__ldg(bp), __ldg(bp + D_MODEL)));
    }
    __syncthreads();

    // A fragments for BOTH token windows -> registers (16 regs)
    unsigned af[2][8];
    #pragma unroll
    for (int w = 0; w < 2; ++w) {
        const unsigned char* ar = sm + OFF_A + (w * 64 + gt * 16 + g) * SA + tig * 4;
        af[w][0] = *(const unsigned*)(ar);
        af[w][1] = *(const unsigned*)(ar + 8 * SA);
        af[w][2] = *(const unsigned*)(ar + 16);
        af[w][3] = *(const unsigned*)(ar + 8 * SA + 16);
        af[w][4] = *(const unsigned*)(ar + 32);
        af[w][5] = *(const unsigned*)(ar + 8 * SA + 32);
        af[w][6] = *(const unsigned*)(ar + 48);
        af[w][7] = *(const unsigned*)(ar + 8 * SA + 48);
    }
    __syncthreads();

    const float scale = __ldg(wscale);

    #pragma unroll
    for (int p = 0; p < 2; ++p) {      // two 64-token passes, full 128 cols
        // pass-1 gathers issue here (q0 already consumed -> regs reused)
        if (p == 1) {
            #pragma unroll
            for (int j = 0; j < 8; ++j) {
                int id = sIds[64 + wid * 8 + j];
                q[j] = __ldcs(reinterpret_cast<const int4*>(
                           wq + (size_t)id * D_MODEL + col0) + lane);
            }
        }

        // ---- MMA: warp quadrant = 16 tokens x 64 cols -> sLora ----
        #pragma unroll
        for (int nb = 0; nb < 8; ++nb) {
            const unsigned char* bb = sm + OFF_B + (cw * 64 + nb * 8 + g) * SB + tig * 4;
            unsigned b0l = *(const unsigned*)(bb);
            unsigned b1l = *(const unsigned*)(bb + 16);
            unsigned b0h = *(const unsigned*)(bb + 32);
            unsigned b1h = *(const unsigned*)(bb + 48);
            float d0 = 0.f, d1 = 0.f, d2 = 0.f, d3 = 0.f;
            mma16816(d0, d1, d2, d3, af[p][0], af[p][1], af[p][2], af[p][3], b0l, b1l);
            mma16816(d0, d1, d2, d3, af[p][4], af[p][5], af[p][6], af[p][7], b0h, b1h);
            int colp = cw * 64 + nb * 8 + 2 * tig;
            int rt   = gt * 16 + g;
            *reinterpret_cast<unsigned*>(sm + OFF_LORA + rt * SL + colp * 2) =
                h2u(__floats2bfloat162_rn(d0, d1));
            *reinterpret_cast<unsigned*>(sm + OFF_LORA + (rt + 8) * SL + colp * 2) =
                h2u(__floats2bfloat162_rn(d2, d3));
        }
        __syncthreads();

        // ---- epilogue: combine + streaming store ----
        #pragma unroll
        for (int j = 0; j < 8; ++j) {
            int tl_loc = wid * 8 + j;                   // 0..63
            int t = t0 + p * 64 + tl_loc;
            uint2 lv = *reinterpret_cast<const uint2*>(
                sm + OFF_LORA + tl_loc * SL + lane * 8);   // cols lane*4..+3
            if (t < ntok) {
                __nv_bfloat162 l0 = u2h(lv.x), l1 = u2h(lv.y);
                float bx = isf ? __int_as_float(q[j].x) : (float)q[j].x;
                float by = isf ? __int_as_float(q[j].y) : (float)q[j].y;
                float bz = isf ? __int_as_float(q[j].z) : (float)q[j].z;
                float bw = isf ? __int_as_float(q[j].w) : (float)q[j].w;
                float4 o;
                o.x = fmaf(bx, scale, __bfloat162float(l0.x));
                o.y = fmaf(by, scale, __bfloat162float(l0.y));
                o.z = fmaf(bz, scale, __bfloat162float(l1.x));
                o.w = fmaf(bw, scale, __bfloat162float(l1.y));
                __stcs(reinterpret_cast<float4*>(
                    out + (size_t)t * D_MODEL + col0 + lane * 4), o);
            }
        }
        __syncthreads();   // protect sLora before next pass overwrites
    }
}

extern "C" void kernel_launch(void* const* d_in, const int* in_sizes, int n_in,
                              void* d_out, int out_size) {
    const int*   ids    = nullptr;
    const int*   wq     = nullptr;
    const float* wscale = nullptr;
    const float* A      = nullptr;
    const float* Bm     = nullptr;

    long long ntok_ll = (long long)out_size / D_MODEL;
    long long wq_sz = 0;
    int wq_idx = -1;
    for (int i = 0; i < n_in; ++i)
        if ((long long)in_sizes[i] > wq_sz) { wq_sz = in_sizes[i]; wq_idx = i; }
    wq = (const int*)d_in[wq_idx];

    for (int i = 0; i < n_in; ++i) {
        if (i == wq_idx) continue;
        long long s = in_sizes[i];
        if (s == 1)                              wscale = (const float*)d_in[i];
        else if (s == ntok_ll)                   ids    = (const int*)d_in[i];
        else if (s == (long long)RANK * D_MODEL) Bm     = (const float*)d_in[i];
        else                                     A      = (const float*)d_in[i];
    }

    const int ntok = (int)ntok_ll;                        // 16384
    dim3 grid(D_MODEL / COLT, (ntok + TOKT - 1) / TOKT);  // (32, 128)
    emb_lora_mma<<<grid, THREADS>>>(ids, wq, wscale, A, Bm, (float*)d_out, ntok);
}

// round 14
// speedup vs baseline: 1.2071x; 1.0445x over previous
#include <cuda_runtime.h>
#include <cuda_bf16.h>
#include <stdint.h>

#define D_MODEL 4096
#define RANK    32
#define TOKT    64           // tokens per CTA tile
#define COLT    256          // columns per CTA tile (1KB gather granule)
#define THREADS 256
#define SA      80           // bytes per sA row: 32 bf16 + 8 pad
#define SB      80           // bytes per sB row: 32 bf16 + 8 pad
#define SL      528          // bytes per sLora row: 256 bf16 + 16 pad

// Layout (38.9KB, 3 CTAs/SM):
//   [16..272)      sIds (64 ints)
//   [1024..21504)  B-tile [n=256][k]
//   [21504..26624) A-tile [tok=64][k] (dead after frag hoist)
//   [21504..38400) sLora 32 rows x 528B (overlays A)
#define OFF_IDS  16
#define OFF_B    1024
#define OFF_A    21504
#define OFF_LORA 21504
#define SM_TOTAL 38912

__device__ __forceinline__ unsigned h2u(__nv_bfloat162 h) {
    return *reinterpret_cast<unsigned*>(&h);
}
__device__ __forceinline__ __nv_bfloat162 u2h(unsigned u) {
    return *reinterpret_cast<__nv_bfloat162*>(&u);
}

__device__ __forceinline__ void mma16816(float& d0, float& d1, float& d2, float& d3,
                                         unsigned a0, unsigned a1, unsigned a2, unsigned a3,
                                         unsigned b0, unsigned b1) {
    asm volatile("mma.sync.aligned.m16n8k16.row.col.f32.bf16.bf16.f32 "
                 "{%0,%1,%2,%3}, {%4,%5,%6,%7}, {%8,%9}, {%0,%1,%2,%3};"
                 : "+f"(d0), "+f"(d1), "+f"(d2), "+f"(d3)
                 : "r"(a0), "r"(a1), "r"(a2), "r"(a3), "r"(b0), "r"(b1));
}

__global__ void __launch_bounds__(THREADS, 3)
emb_lora_mma(const int* __restrict__ ids, const int* __restrict__ wq,
             const float* __restrict__ wscale, const float* __restrict__ A,
             const float* __restrict__ Bm, float* __restrict__ out, int ntok)
{
    __shared__ __align__(16) unsigned char sm[SM_TOTAL];

    const int tid  = threadIdx.x;
    const int wid  = tid >> 5;
    const int lane = tid & 31;
    const int g    = lane >> 2;
    const int tig  = lane & 3;
    const int gt   = wid & 1;         // warp's 16-token sub-block within pass
    const int cw   = wid >> 1;        // warp's 64-col quarter (0..3)
    const int t0   = blockIdx.y * TOKT;
    const int col0 = blockIdx.x * COLT;
    int* sIds = (int*)(sm + OFF_IDS);

    if (tid < TOKT) {
        int t = t0 + tid;
        sIds[tid] = (t < ntok) ? __ldg(ids + t) : 0;
    }

    int isf = 0;
    #pragma unroll
    for (int i = 0; i < 16; ++i) {
        unsigned u = __ldg((const unsigned*)wq + i);
        if (u == 0u) continue;
        unsigned e = (u >> 23) & 0xFFu;
        isf = (e != 0u && e != 0xFFu);
        break;
    }
    __syncthreads();

    // ---- pass-0 gathers FIRST (drain during prologue): 4 tokens x 1KB/warp ----
    int4 q[4][2];
    #pragma unroll
    for (int j = 0; j < 4; ++j) {
        int id = sIds[wid * 4 + j];
        const int4* rp = reinterpret_cast<const int4*>(wq + (size_t)id * D_MODEL + col0);
        q[j][0] = __ldcs(rp + lane);
        q[j][1] = __ldcs(rp + 32 + lane);
    }

    // A-tile [tok=64][k], SCALING=0.5 folded (exact pow2)
    #pragma unroll
    for (int i = 0; i < 4; ++i) {
        int p  = tid + i * THREADS;          // 0..1023
        int tl = p >> 4, kp = p & 15;
        int id = sIds[tl];
        float2 v = *reinterpret_cast<const float2*>(A + (size_t)id * RANK + 2 * kp);
        *reinterpret_cast<unsigned*>(sm + OFF_A + tl * SA + kp * 4) =
            h2u(__floats2bfloat162_rn(v.x * 0.5f, v.y * 0.5f));
    }
    // B-tile [n=256][k] (transpose of Bm[k][n]; L2-resident across grid.y)
    #pragma unroll
    for (int i = 0; i < 16; ++i) {
        int n  = tid;                        // coalesced in n
        int kp = i;
        const float* bp = Bm + (size_t)(2 * kp) * D_MODEL + col0 + n;
        *reinterpret_cast<unsigned*>(sm + OFF_B + n * SB + kp * 4) =
            h2u(__floats2bfloat162_rn(__ldg(bp), __ldg(bp + D_MODEL)));
    }
    __syncthreads();

    // A fragments for BOTH passes -> registers (16 regs)
    unsigned af[2][8];
    #pragma unroll
    for (int w = 0; w < 2; ++w) {
        const unsigned char* ar = sm + OFF_A + (w * 32 + gt * 16 + g) * SA + tig * 4;
        af[w][0] = *(const unsigned*)(ar);
        af[w][1] = *(const unsigned*)(ar + 8 * SA);
        af[w][2] = *(const unsigned*)(ar + 16);
        af[w][3] = *(const unsigned*)(ar + 8 * SA + 16);
        af[w][4] = *(const unsigned*)(ar + 32);
        af[w][5] = *(const unsigned*)(ar + 8 * SA + 32);
        af[w][6] = *(const unsigned*)(ar + 48);
        af[w][7] = *(const unsigned*)(ar + 8 * SA + 48);
    }
    __syncthreads();

    const float scale = __ldg(wscale);

    #pragma unroll
    for (int p = 0; p < 2; ++p) {      // two 32-token passes, full 256 cols
        // pass-1 gathers issue here (pass-0 q consumed by then -> regs reused)
        if (p == 1) {
            #pragma unroll
            for (int j = 0; j < 4; ++j) {
                int id = sIds[32 + wid * 4 + j];
                const int4* rp = reinterpret_cast<const int4*>(
                    wq + (size_t)id * D_MODEL + col0);
                q[j][0] = __ldcs(rp + lane);
                q[j][1] = __ldcs(rp + 32 + lane);
            }
        }

        // ---- MMA: warp quadrant = 16 tokens x 64 cols -> sLora ----
        #pragma unroll
        for (int nb = 0; nb < 8; ++nb) {
            const unsigned char* bb = sm + OFF_B + (cw * 64 + nb * 8 + g) * SB + tig * 4;
            unsigned b0l = *(const unsigned*)(bb);
            unsigned b1l = *(const unsigned*)(bb + 16);
            unsigned b0h = *(const unsigned*)(bb + 32);
            unsigned b1h = *(const unsigned*)(bb + 48);
            float d0 = 0.f, d1 = 0.f, d2 = 0.f, d3 = 0.f;
            mma16816(d0, d1, d2, d3, af[p][0], af[p][1], af[p][2], af[p][3], b0l, b1l);
            mma16816(d0, d1, d2, d3, af[p][4], af[p][5], af[p][6], af[p][7], b0h, b1h);
            int colp = cw * 64 + nb * 8 + 2 * tig;   // col (0..255)
            int rt   = gt * 16 + g;                  // local row (0..31)
            *reinterpret_cast<unsigned*>(sm + OFF_LORA + rt * SL + colp * 2) =
                h2u(__floats2bfloat162_rn(d0, d1));
            *reinterpret_cast<unsigned*>(sm + OFF_LORA + (rt + 8) * SL + colp * 2) =
                h2u(__floats2bfloat162_rn(d2, d3));
        }
        __syncthreads();

        // ---- epilogue: combine + streaming 1KB-contiguous row stores ----
        #pragma unroll
        for (int j = 0; j < 4; ++j) {
            int tl_loc = wid * 4 + j;                // 0..31
            int t = t0 + p * 32 + tl_loc;
            #pragma unroll
            for (int h = 0; h < 2; ++h) {
                uint2 lv = *reinterpret_cast<const uint2*>(
                    sm + OFF_LORA + tl_loc * SL + h * 256 + lane * 8);
                if (t < ntok) {
                    __nv_bfloat162 l0 = u2h(lv.x), l1 = u2h(lv.y);
                    int4 qq = q[j][h];
                    float bx = isf ? __int_as_float(qq.x) : (float)qq.x;
                    float by = isf ? __int_as_float(qq.y) : (float)qq.y;
                    float bz = isf ? __int_as_float(qq.z) : (float)qq.z;
                    float bw = isf ? __int_as_float(qq.w) : (float)qq.w;
                    float4 o;
                    o.x = fmaf(bx, scale, __bfloat162float(l0.x));
                    o.y = fmaf(by, scale, __bfloat162float(l0.y));
                    o.z = fmaf(bz, scale, __bfloat162float(l1.x));
                    o.w = fmaf(bw, scale, __bfloat162float(l1.y));
                    __stcs(reinterpret_cast<float4*>(
                        out + (size_t)t * D_MODEL + col0 + h * 128 + lane * 4), o);
                }
            }
        }
        __syncthreads();   // protect sLora before next pass overwrites
    }
}

extern "C" void kernel_launch(void* const* d_in, const int* in_sizes, int n_in,
                              void* d_out, int out_size) {
    const int*   ids    = nullptr;
    const int*   wq     = nullptr;
    const float* wscale = nullptr;
    const float* A      = nullptr;
    const float* Bm     = nullptr;

    long long ntok_ll = (long long)out_size / D_MODEL;
    long long wq_sz = 0;
    int wq_idx = -1;
    for (int i = 0; i < n_in; ++i)
        if ((long long)in_sizes[i] > wq_sz) { wq_sz = in_sizes[i]; wq_idx = i; }
    wq = (const int*)d_in[wq_idx];

    for (int i = 0; i < n_in; ++i) {
        if (i == wq_idx) continue;
        long long s = in_sizes[i];
        if (s == 1)                              wscale = (const float*)d_in[i];
        else if (s == ntok_ll)                   ids    = (const int*)d_in[i];
        else if (s == (long long)RANK * D_MODEL) Bm     = (const float*)d_in[i];
        else                                     A      = (const float*)d_in[i];
    }

    const int ntok = (int)ntok_ll;                        // 16384
    dim3 grid(D_MODEL / COLT, (ntok + TOKT - 1) / TOKT);  // (16, 256)
    emb_lora_mma<<<grid, THREADS>>>(ids, wq, wscale, A, Bm, (float*)d_out, ntok);
}